// round 12
// baseline (speedup 1.0000x reference)
#include <cuda_runtime.h>

// ForgetMult: h_t = f_t*x_t + (1-f_t)*h_{t-1}
// f,x: (4096, 16, 512) fp32. out inclusive, h_0 = hidden_init.
//
// Single-pass chunked scan, float4 channels, no staging (phase 4 re-reads
// f,x from L2). vs R10 (96.6us):
//   - Flags transposed to [tile][tblk]; look-back wait done LANE-PARALLEL
//     (16 lanes poll 16 predecessor flags concurrently + ballot) instead of
//     <=15 serial L2 round-trips.
//   - Phase-2 scan ping-pong buffered: 1 barrier per round (4 vs 8).

#define SEQ_LEN  4096
#define C4       2048                  // float4 channels
#define SL       16                    // timesteps per thread
#define SUBS     16                    // sub-chunks per block
#define TILE_C4  16                    // f4 channels per block (64 fp32)
#define TB       (SL * SUBS)           // 256 timesteps per block
#define TBLKS    (SEQ_LEN / TB)        // 16
#define TILES    (C4 / TILE_C4)        // 128
#define NTHREADS (TILE_C4 * SUBS)      // 256

__device__ float4 g_aggA[TBLKS * C4];
__device__ float4 g_aggB[TBLKS * C4];
__device__ float4 g_prefH[C4];            // h at end of time-block 0
__device__ int    g_flag[TILES * TBLKS];  // [tile][tblk]; 0=none 1=agg 2=prefix

__device__ __forceinline__ float4 f4_fma(float4 a, float4 h, float4 b) {
    return make_float4(fmaf(a.x, h.x, b.x), fmaf(a.y, h.y, b.y),
                       fmaf(a.z, h.z, b.z), fmaf(a.w, h.w, b.w));
}
__device__ __forceinline__ float4 f4_mul(float4 a, float4 b) {
    return make_float4(a.x * b.x, a.y * b.y, a.z * b.z, a.w * b.w);
}
__device__ __forceinline__ int ld_acquire_gpu(const int* p) {
    int v;
    asm volatile("ld.acquire.gpu.global.b32 %0, [%1];" : "=r"(v) : "l"(p) : "memory");
    return v;
}
__device__ __forceinline__ void st_release_gpu(int* p, int v) {
    asm volatile("st.release.gpu.global.b32 [%0], %1;" :: "l"(p), "r"(v) : "memory");
}

__global__ void reset_flags_kernel()
{
    int i = blockIdx.x * blockDim.x + threadIdx.x;
    if (i < TILES * TBLKS) g_flag[i] = 0;
}

__global__ __launch_bounds__(NTHREADS, 4)
void forget_mult_v11_kernel(
    const float4* __restrict__ f,
    const float4* __restrict__ x,
    const float4* __restrict__ h0,
    float4* __restrict__ out)
{
    __shared__ float4 sA[2][SUBS * TILE_C4];   // ping-pong scan buffers
    __shared__ float4 sB[2][SUBS * TILE_C4];
    __shared__ float4 sHin[TILE_C4];

    const int tid  = threadIdx.x;
    const int c    = tid & (TILE_C4 - 1);       // f4 channel within tile
    const int s    = tid >> 4;                  // sub-chunk index
    const int tile = blockIdx.x >> 4;           // / TBLKS
    const int tblk = blockIdx.x & (TBLKS - 1);  // fastest-varying in bid

    const int cg = tile * TILE_C4 + c;
    const int t0 = tblk * TB + s * SL;

    const float4* fp = f + (size_t)t0 * C4 + cg;
    const float4* xp = x + (size_t)t0 * C4 + cg;

    // ---- Phase 1: stream loads (lines stay L2-resident), fold composite ----
    float4 cA = make_float4(1.f, 1.f, 1.f, 1.f);
    float4 cB = make_float4(0.f, 0.f, 0.f, 0.f);
#pragma unroll
    for (int i = 0; i < SL; i++) {
        float4 ft = fp[(size_t)i * C4];   // default caching -> L2 keeps it
        float4 xt = xp[(size_t)i * C4];
        float4 a = make_float4(1.f - ft.x, 1.f - ft.y, 1.f - ft.z, 1.f - ft.w);
        float4 b = f4_mul(ft, xt);
        cB = f4_fma(a, cB, b);
        cA = f4_mul(cA, a);
    }

    // ---- Phase 2: Hillis-Steele, ping-pong (1 barrier per round) ----
    int p = 0;
    sA[0][s * TILE_C4 + c] = cA;
    sB[0][s * TILE_C4 + c] = cB;
    __syncthreads();
#pragma unroll
    for (int d = 1; d < SUBS; d <<= 1) {
        if (s >= d) {
            float4 pA = sA[p][(s - d) * TILE_C4 + c];
            float4 pB = sB[p][(s - d) * TILE_C4 + c];
            cB = f4_fma(cA, pB, cB);   // cur ∘ prev
            cA = f4_mul(cA, pA);
        }
        sA[p ^ 1][s * TILE_C4 + c] = cA;
        sB[p ^ 1][s * TILE_C4 + c] = cB;
        p ^= 1;
        __syncthreads();
    }
    float4 exA = make_float4(1.f, 1.f, 1.f, 1.f);
    float4 exB = make_float4(0.f, 0.f, 0.f, 0.f);
    if (s > 0) {
        exA = sA[p][(s - 1) * TILE_C4 + c];
        exB = sB[p][(s - 1) * TILE_C4 + c];
    }

    // ---- Phase 3: look-back, lane-parallel wait (lanes 0..15 of warp 0) ----
    if (tid < TILE_C4) {
        const float4 blkA = sA[p][(SUBS - 1) * TILE_C4 + tid];
        const float4 blkB = sB[p][(SUBS - 1) * TILE_C4 + tid];
        const int cg0   = tile * TILE_C4 + tid;
        const int fbase = tile * TBLKS;
        float4 hin_blk;
        if (tblk == 0) {
            hin_blk = h0[cg0];
            g_prefH[cg0] = f4_fma(blkA, hin_blk, blkB);
            __syncwarp(0x0000FFFFu);
            if (tid == 0)
                st_release_gpu(&g_flag[fbase + 0], 2);
        } else {
            g_aggA[(size_t)tblk * C4 + cg0] = blkA;
            g_aggB[(size_t)tblk * C4 + cg0] = blkB;
            __syncwarp(0x0000FFFFu);
            if (tid == 0)
                st_release_gpu(&g_flag[fbase + tblk], 1);

            // Parallel wait: lane j polls predecessor j (tblk <= 15, so one
            // flag per lane). Ballot collapses the wait to ~1 round-trip.
            {
                const int j    = tid;            // predecessor index
                const int need = (j == 0) ? 2 : 1;
                bool ok;
                do {
                    ok = (j >= tblk) || (ld_acquire_gpu(&g_flag[fbase + j]) >= need);
                } while (!__all_sync(0x0000FFFFu, ok));
            }
            __syncwarp(0x0000FFFFu);   // order acquires before cross-lane agg reads

            // Fold: aggregate loads independent across j -> overlapped.
            float4 accA = make_float4(1.f, 1.f, 1.f, 1.f);
            float4 accB = make_float4(0.f, 0.f, 0.f, 0.f);
#pragma unroll 5
            for (int j = tblk - 1; j >= 1; j--) {
                float4 aj = g_aggA[(size_t)j * C4 + cg0];
                float4 bj = g_aggB[(size_t)j * C4 + cg0];
                accB = f4_fma(accA, bj, accB);
                accA = f4_mul(accA, aj);
            }
            float4 hpre = g_prefH[cg0];
            hin_blk = f4_fma(accA, hpre, accB);
        }
        sHin[tid] = hin_blk;
    }
    __syncthreads();

    // ---- Phase 4: re-read f,x (L2-hot), rebuild a,b, replay, store ----
    float4 h = f4_fma(exA, sHin[c], exB);
    float4* op = out + (size_t)t0 * C4 + cg;
#pragma unroll
    for (int i = 0; i < SL; i++) {
        float4 ft = __ldcs(fp + (size_t)i * C4);   // 2nd use: evict-first
        float4 xt = __ldcs(xp + (size_t)i * C4);
        float4 a = make_float4(1.f - ft.x, 1.f - ft.y, 1.f - ft.z, 1.f - ft.w);
        float4 b = f4_mul(ft, xt);
        h = f4_fma(a, h, b);
        __stcs(op + (size_t)i * C4, h);
    }
}

extern "C" void kernel_launch(void* const* d_in, const int* in_sizes, int n_in,
                              void* d_out, int out_size)
{
    const float4* f  = (const float4*)d_in[0];
    const float4* x  = (const float4*)d_in[1];
    const float4* h0 = (const float4*)d_in[2];
    float4* out = (float4*)d_out;

    reset_flags_kernel<<<(TILES * TBLKS + 255) / 256, 256>>>();

    dim3 grid(TILES * TBLKS);   // tblk fastest -> predecessors at lower bid
    dim3 block(NTHREADS);
    forget_mult_v11_kernel<<<grid, block>>>(f, x, h0, out);
}